// round 16
// baseline (speedup 1.0000x reference)
#include <cuda_runtime.h>
#include <cstdint>
#include <cstddef>

#define NROWS 8192
#define ROW_F4 2048              // NROWS/4
#define ROW_SHIFT 11
#define NN_F4 (NROWS * (size_t)NROWS / 4)
#define NCLS 128
#define CAP_M 1024               // smem member-list capacity (mean 64, absurd margin)

__device__ unsigned char g_cls[NROWS];
__device__ float4        g_params[NROWS];   // {pg, ng, rv, pad}

// ---- k_prep: ONE prolog kernel, block per class ----
// Block c: dtype probe; scan all targets, build smem member list of class c;
// then one thread per member row computes pos_cnt over the member list and
// writes that row's params + class byte. No global scratch state at all.
__global__ __launch_bounds__(256) void k_prep(const int* __restrict__ w,
                                              const float* __restrict__ sim) {
    __shared__ unsigned short sh_mem[CAP_M];
    __shared__ int sh_cnt;
    __shared__ int sh32;
    int t = threadIdx.x;
    int c = blockIdx.x;

    if (t == 0) { sh_cnt = 0; sh32 = 0; }
    __syncthreads();
    // Dtype probe reads only words < NROWS (in-bounds for both dtypes):
    // int64 values in [0,128) => odd 32-bit words all zero; int32 => odd
    // words are random classes, P(all 128 zero) = 128^-128 ~ 0.
    if (t < 128 && w[2 * t + 1] != 0) sh32 = 1;
    __syncthreads();
    int is32 = sh32;

    // scan all rows for class == c (coalesced; L2-hot after first wave)
#pragma unroll 4
    for (int k = 0; k < NROWS / 256; ++k) {
        int i = t + k * 256;
        int v = (is32 ? w[i] : w[2 * i]) & 127;
        if (v == c) {
            int p = atomicAdd(&sh_cnt, 1);
            if (p < CAP_M) sh_mem[p] = (unsigned short)i;
        }
    }
    __syncthreads();

    int m   = sh_cnt;
    int lim = (m < CAP_M) ? m : CAP_M;
    int negraw = NROWS - m;
    float rv = (negraw > 0) ? 1.0f : 0.0f;
    float ng = 40.0f * rv / (float)((negraw > 1) ? negraw : 1);

    // one thread per member row: dense independent loads, compiler-pipelined
    for (int rr = t; rr < lim; rr += 256) {
        int row = sh_mem[rr];
        const float* rowp = sim + (size_t)row * NROWS;
        int pc = 0;
#pragma unroll 8
        for (int j = 0; j < lim; ++j)
            pc += (rowp[sh_mem[j]] < 1.0f) ? 1 : 0;   // includes diagonal, like reference
        float pg = -2.0f * rv / (float)((pc > 1) ? pc : 1);
        g_params[row] = make_float4(pg, ng, rv, 0.0f);
        g_cls[row] = (unsigned char)c;
    }
}

// ---- per-element math ----
__device__ __forceinline__ void elem(float simv, bool same,
                                     float pg, float ng, float rv,
                                     float& L, float& G) {
    float s = simv - 0.5f;
    float z = same ? (-2.0f * s) : (40.0f * s);
    bool active = (!same) || (simv < 1.0f);
    float t   = __expf(-fabsf(z));
    float op  = 1.0f + t;
    float inv = __fdividef(1.0f, op);
    float sp  = fmaxf(z, 0.0f) + __logf(op);          // stable softplus(z)
    float sg  = ((z >= 0.0f) ? 1.0f : t) * inv;       // stable sigmoid(z)
    float cf  = same ? pg : ng;
    L = active ? sp * rv : 0.0f;
    G = active ? cf * sg : 0.0f;
}

// ---- main streaming kernel: PRISTINE hot path (116us, 81% DRAM) ----
__global__ __launch_bounds__(256) void k_main(const float* __restrict__ sim,
                                              float* __restrict__ out) {
    cudaGridDependencySynchronize();
    int idx  = blockIdx.x * blockDim.x + threadIdx.x;   // float4 index
    int row  = idx >> ROW_SHIFT;
    int col4 = idx & (ROW_F4 - 1);

    float4 sv = __ldcs(reinterpret_cast<const float4*>(sim) + idx);
    uchar4 cj = reinterpret_cast<const uchar4*>(g_cls)[col4];
    int    ci = g_cls[row];
    float4 p  = g_params[row];

    float4 Lo, Gr;
    elem(sv.x, cj.x == ci, p.x, p.y, p.z, Lo.x, Gr.x);
    elem(sv.y, cj.y == ci, p.x, p.y, p.z, Lo.y, Gr.y);
    elem(sv.z, cj.z == ci, p.x, p.y, p.z, Lo.z, Gr.z);
    elem(sv.w, cj.w == ci, p.x, p.y, p.z, Lo.w, Gr.w);

    float4* lossb = reinterpret_cast<float4*>(out);
    float4* gradb = lossb + NN_F4;
    __stcs(lossb + idx, Lo);
    __stcs(gradb + idx, Gr);
}

extern "C" void kernel_launch(void* const* d_in, const int* in_sizes, int n_in,
                              void* d_out, int out_size) {
    const float* sim = (const float*)d_in[0];
    const int*   tgw = (const int*)d_in[1];     // int32 view of targets
    float*       out = (float*)d_out;

    k_prep<<<NCLS, 256>>>(tgw, sim);

    cudaLaunchAttribute attr[1];
    attr[0].id = cudaLaunchAttributeProgrammaticStreamSerialization;
    attr[0].val.programmaticStreamSerializationAllowed = 1;
    cudaLaunchConfig_t cfg = {};
    cfg.gridDim  = dim3((unsigned)(NN_F4 / 256), 1, 1);
    cfg.blockDim = dim3(256, 1, 1);
    cfg.attrs    = attr;
    cfg.numAttrs = 1;
    cudaLaunchKernelEx(&cfg, k_main, sim, out);
}